// round 13
// baseline (speedup 1.0000x reference)
#include <cuda_runtime.h>
#include <cuda_fp16.h>
#include <math.h>

// Problem dims (fixed by the reference): N=50000, E=800000, G=512.
#define NMAX 50048
#define GMAX 512
#define MAXD 96     // per-node bucket capacity; deg ~ Poisson(16), P(>=96) ~ 0

// ---- packed fp32x2 helpers (sm_103a FFMA2; exact fp32) ----
#define FFMA2(d, a, b) \
    asm("fma.rn.f32x2 %0, %1, %2, %0;" : "+l"(d) : "l"(a), "l"(b))
#define PACK_DUP(d, x) \
    asm("mov.b64 %0, {%1, %1};" : "=l"(d) : "r"(__float_as_uint(x)))
#define UNPACK2(lo, hi, d) \
    asm("mov.b64 {%0, %1}, %2;" : "=r"(lo), "=r"(hi) : "l"(d))

// ---- scratch (device globals; no allocation allowed) ----
__device__ int     g_is64;               // 1 if index buffers are int64
__device__ int     g_deg[NMAX];
__device__ float   g_dinv[NMAX];
__device__ float4  g_px[NMAX];           // dinv[u] * x[u] padded to float4 (w=0)
__device__ int     g_slot[NMAX * MAXD];  // bucketed CSR-by-dst (src only)
__device__ __half2 g_ps1[NMAX * 16];     // dinv[u] * relu(h1[u])  (32 fp16)
__device__ __half2 g_ps2[NMAX * 32];     // dinv[u] * relu(h2[u])  (64 fp16)
__device__ __half2 g_h3[NMAX * 64];      // relu(h3[u])            (128 fp16)

__device__ __forceinline__ int idx_at(const void* p, long long i, int is64) {
    if (is64) return (int)((const long long*)p)[i];
    return ((const int*)p)[i];
}
__device__ __forceinline__ int clampi(int v, int lo, int hi) {
    return v < lo ? lo : (v > hi ? hi : v);
}

// ============================================================
// 0) zero degrees + detect index dtype
// ============================================================
__global__ void k_prep(const int* __restrict__ ebuf, int E, int N) {
    int i = blockIdx.x * blockDim.x + threadIdx.x;
    if (i < N) g_deg[i] = 0;
    if (blockIdx.x == 0) {
        __shared__ int s_nz;
        if (threadIdx.x == 0) s_nz = 0;
        __syncthreads();
        int nz = 0;
        int stride = (2 * E) / 4096;
        for (int k = threadIdx.x; k < 4096; k += blockDim.x) {
            long long w = (long long)k * stride | 1LL;
            if (w < 2LL * E) nz |= (ebuf[w] != 0);
        }
        if (nz) atomicOr(&s_nz, 1);
        __syncthreads();
        if (threadIdx.x == 0) g_is64 = (s_nz == 0) ? 1 : 0;
    }
}

// 1) bucket scatter: count + fill in ONE pass
__global__ void k_fill(const void* __restrict__ ei, int E, int N) {
    int e = blockIdx.x * blockDim.x + threadIdx.x;
    if (e < E) {
        int is64 = g_is64;
        int s = clampi(idx_at(ei, e, is64), 0, N - 1);
        int d = clampi(idx_at(ei, (long long)E + e, is64), 0, N - 1);
        int c = atomicAdd(&g_deg[d], 1);
        if (c < MAXD) g_slot[d * MAXD + c] = s;
    }
}

// 2) dinv = rsqrt(deg+1); pre-scale node features into float4
__global__ void k_scale(const float* __restrict__ x, int N) {
    int i = blockIdx.x * blockDim.x + threadIdx.x;
    if (i < N) {
        float di = rsqrtf((float)g_deg[i] + 1.0f);  // +1 self-loop
        g_dinv[i] = di;
        g_px[i] = make_float4(di * x[i * 3], di * x[i * 3 + 1], di * x[i * 3 + 2], 0.f);
    }
}

// ============================================================
// Layer 1: agg(3) @ W1(3x32) + b1, relu, pre-scale -> g_ps1 (fp16)
// FOUR nodes per warp iteration (interleaved latency chains).
// ============================================================
__global__ void __launch_bounds__(256) k_layer1(const float* __restrict__ W1,
                                                const float* __restrict__ b1, int N) {
    __shared__ float sW[96];
    __shared__ float sb[32];
    int t = threadIdx.x;
    if (t < 96) sW[t] = W1[t];
    if (t < 32) sb[t] = b1[t];
    __syncthreads();
    int lane = t & 31;
    int warp0 = (blockIdx.x * blockDim.x + t) >> 5;
    int nwarps = (gridDim.x * blockDim.x) >> 5;
    int nquads = (N + 3) >> 2;
    for (int qd = warp0; qd < nquads; qd += nwarps) {
        int n0 = 4 * qd;
        int deg[4], base[4];
        float ax[4], ay[4], az[4];
        int dmax = 0;
#pragma unroll
        for (int u = 0; u < 4; u++) {
            int nu = n0 + u;
            deg[u] = (nu < N) ? min(g_deg[nu], MAXD) : 0;
            base[u] = nu * MAXD;
            ax[u] = 0.f; ay[u] = 0.f; az[u] = 0.f;
            dmax = max(dmax, deg[u]);
        }
        for (int j = lane; j < dmax; j += 32) {
#pragma unroll
            for (int u = 0; u < 4; u++) {
                if (j < deg[u]) {
                    float4 p = g_px[g_slot[base[u] + j]];
                    ax[u] += p.x; ay[u] += p.y; az[u] += p.z;
                }
            }
        }
#pragma unroll
        for (int st = 16; st >= 1; st >>= 1) {
#pragma unroll
            for (int u = 0; u < 4; u++) {
                ax[u] += __shfl_xor_sync(0xffffffffu, ax[u], st);
                ay[u] += __shfl_xor_sync(0xffffffffu, ay[u], st);
                az[u] += __shfl_xor_sync(0xffffffffu, az[u], st);
            }
        }
        if (lane < 16) {
            int f = 2 * lane;
            float w0 = sW[f],     w1 = sW[32 + f],     w2 = sW[64 + f];
            float v0 = sW[f + 1], v1 = sW[32 + f + 1], v2 = sW[64 + f + 1];
            float bb0 = sb[f], bb1 = sb[f + 1];
#pragma unroll
            for (int u = 0; u < 4; u++) {
                int nu = n0 + u;
                if (nu < N) {
                    float di = g_dinv[nu];
                    float4 self = g_px[nu];
                    float a0 = di * (ax[u] + self.x);
                    float a1 = di * (ay[u] + self.y);
                    float a2 = di * (az[u] + self.z);
                    float o0 = bb0 + a0 * w0 + a1 * w1 + a2 * w2;
                    float o1 = bb1 + a0 * v0 + a1 * v1 + a2 * v2;
                    g_ps1[nu * 16 + lane] =
                        __floats2half2_rn(di * fmaxf(o0, 0.f), di * fmaxf(o1, 0.f));
                }
            }
        }
    }
}

// ============================================================
// Layer 2: agg(32) @ W2(32x64) + b2, relu, pre-scale -> g_ps2 (fp16)
// Dual-node interleaved gather; sequential FFMA2 GEMVs. 512 thr bounded.
// ============================================================
__global__ void __launch_bounds__(512) k_layer2(const float* __restrict__ W2,
                                                const float* __restrict__ b2, int N) {
    __shared__ __align__(16) float sW[32 * 64];   // 8 KB
    __shared__ __align__(16) float sb[64];
    int t = threadIdx.x;
    for (int i = t; i < 32 * 64; i += blockDim.x) sW[i] = W2[i];
    if (t < 64) sb[t] = b2[t];
    __syncthreads();
    int lane = t & 31;
    int warp0 = (blockIdx.x * blockDim.x + t) >> 5;
    int nwarps = (gridDim.x * blockDim.x) >> 5;
    int q = lane & 15, p = lane >> 4;
    const unsigned long long* sWp = (const unsigned long long*)sW;
    int npairs = (N + 1) >> 1;
    for (int pr = warp0; pr < npairs; pr += nwarps) {
        int nA = 2 * pr;
        int nB = nA + 1;
        bool hasB = (nB < N);
        int degA = min(g_deg[nA], MAXD);
        int degB = hasB ? min(g_deg[nB], MAXD) : 0;
        int baseA = nA * MAXD, baseB = nB * MAXD;
        float axA = 0.f, ayA = 0.f, axB = 0.f, ayB = 0.f;
        int dmax = max(degA, degB);
        for (int j = p; j < dmax; j += 2) {
            if (j < degA) {
                float2 f = __half22float2(g_ps1[(size_t)g_slot[baseA + j] * 16 + q]);
                axA += f.x; ayA += f.y;
            }
            if (j < degB) {
                float2 f = __half22float2(g_ps1[(size_t)g_slot[baseB + j] * 16 + q]);
                axB += f.x; ayB += f.y;
            }
        }
        axA += __shfl_xor_sync(0xffffffffu, axA, 16);
        ayA += __shfl_xor_sync(0xffffffffu, ayA, 16);
        axB += __shfl_xor_sync(0xffffffffu, axB, 16);
        ayB += __shfl_xor_sync(0xffffffffu, ayB, 16);
        float diA = g_dinv[nA];
        float2 selfA = __half22float2(g_ps1[(size_t)nA * 16 + q]);
        float accxA = diA * (axA + selfA.x);
        float accyA = diA * (ayA + selfA.y);
        float diB = 0.f, accxB = 0.f, accyB = 0.f;
        if (hasB) {
            diB = g_dinv[nB];
            float2 selfB = __half22float2(g_ps1[(size_t)nB * 16 + q]);
            accxB = diB * (axB + selfB.x);
            accyB = diB * (ayB + selfB.y);
        }
        // GEMV A
        unsigned long long oA = ((const unsigned long long*)sb)[lane];
#pragma unroll
        for (int k = 0; k < 16; k++) {
            float axk = __shfl_sync(0xffffffffu, accxA, k);
            float ayk = __shfl_sync(0xffffffffu, accyA, k);
            unsigned long long ax2, ay2;
            PACK_DUP(ax2, axk);
            PACK_DUP(ay2, ayk);
            FFMA2(oA, ax2, sWp[(2 * k) * 32 + lane]);
            FFMA2(oA, ay2, sWp[(2 * k + 1) * 32 + lane]);
        }
        unsigned int u0, u1;
        UNPACK2(u0, u1, oA);
        g_ps2[(size_t)nA * 32 + lane] = __floats2half2_rn(
            diA * fmaxf(__uint_as_float(u0), 0.f),
            diA * fmaxf(__uint_as_float(u1), 0.f));
        // GEMV B
        if (hasB) {
            unsigned long long oB = ((const unsigned long long*)sb)[lane];
#pragma unroll
            for (int k = 0; k < 16; k++) {
                float axk = __shfl_sync(0xffffffffu, accxB, k);
                float ayk = __shfl_sync(0xffffffffu, accyB, k);
                unsigned long long ax2, ay2;
                PACK_DUP(ax2, axk);
                PACK_DUP(ay2, ayk);
                FFMA2(oB, ax2, sWp[(2 * k) * 32 + lane]);
                FFMA2(oB, ay2, sWp[(2 * k + 1) * 32 + lane]);
            }
            UNPACK2(u0, u1, oB);
            g_ps2[(size_t)nB * 32 + lane] = __floats2half2_rn(
                diB * fmaxf(__uint_as_float(u0), 0.f),
                diB * fmaxf(__uint_as_float(u1), 0.f));
        }
    }
}

// ============================================================
// Layer 3: agg(64 = one 128B row) @ W3(64x128) + b3, relu -> g_h3 (fp16)
// Dual-node interleaved gather (2 chains each); sequential FFMA2 GEMVs.
// ============================================================
__global__ void __launch_bounds__(512) k_layer3(const float* __restrict__ W3,
                                                const float* __restrict__ b3, int N) {
    __shared__ __align__(16) float sW[64 * 128];  // 32 KB
    __shared__ __align__(16) float sb[128];
    int t = threadIdx.x;
    for (int i = t; i < 64 * 128; i += blockDim.x) sW[i] = W3[i];
    if (t < 128) sb[t] = b3[t];
    __syncthreads();
    int lane = t & 31;
    int warp0 = (blockIdx.x * blockDim.x + t) >> 5;
    int nwarps = (gridDim.x * blockDim.x) >> 5;
    const ulonglong2* sWq = (const ulonglong2*)sW;
    int npairs = (N + 1) >> 1;
    for (int pr = warp0; pr < npairs; pr += nwarps) {
        int nA = 2 * pr;
        int nB = nA + 1;
        bool hasB = (nB < N);
        int degA = min(g_deg[nA], MAXD);
        int degB = hasB ? min(g_deg[nB], MAXD) : 0;
        int baseA = nA * MAXD, baseB = nB * MAXD;
        float axA0 = 0.f, ayA0 = 0.f, axA1 = 0.f, ayA1 = 0.f;
        float axB0 = 0.f, ayB0 = 0.f, axB1 = 0.f, ayB1 = 0.f;
        int dmax = max(degA, degB);
        for (int j = 0; j < dmax; j += 2) {
            if (j < degA) {
                float2 f = __half22float2(g_ps2[(size_t)g_slot[baseA + j] * 32 + lane]);
                axA0 += f.x; ayA0 += f.y;
            }
            if (j + 1 < degA) {
                float2 f = __half22float2(g_ps2[(size_t)g_slot[baseA + j + 1] * 32 + lane]);
                axA1 += f.x; ayA1 += f.y;
            }
            if (j < degB) {
                float2 f = __half22float2(g_ps2[(size_t)g_slot[baseB + j] * 32 + lane]);
                axB0 += f.x; ayB0 += f.y;
            }
            if (j + 1 < degB) {
                float2 f = __half22float2(g_ps2[(size_t)g_slot[baseB + j + 1] * 32 + lane]);
                axB1 += f.x; ayB1 += f.y;
            }
        }
        float diA = g_dinv[nA];
        float2 selfA = __half22float2(g_ps2[(size_t)nA * 32 + lane]);
        float accxA = diA * ((axA0 + axA1) + selfA.x);
        float accyA = diA * ((ayA0 + ayA1) + selfA.y);
        float accxB = 0.f, accyB = 0.f;
        if (hasB) {
            float diB = g_dinv[nB];
            float2 selfB = __half22float2(g_ps2[(size_t)nB * 32 + lane]);
            accxB = diB * ((axB0 + axB1) + selfB.x);
            accyB = diB * ((ayB0 + ayB1) + selfB.y);
        }
        // GEMV + store for node A
        {
            ulonglong2 bb = ((const ulonglong2*)sb)[lane];
            unsigned long long o01 = bb.x, o23 = bb.y;
#pragma unroll
            for (int k = 0; k < 32; k++) {
                float axk = __shfl_sync(0xffffffffu, accxA, k);
                float ayk = __shfl_sync(0xffffffffu, accyA, k);
                unsigned long long ax2p, ay2p;
                PACK_DUP(ax2p, axk);
                PACK_DUP(ay2p, ayk);
                ulonglong2 u = sWq[(2 * k) * 32 + lane];
                ulonglong2 v = sWq[(2 * k + 1) * 32 + lane];
                FFMA2(o01, ax2p, u.x);
                FFMA2(o23, ax2p, u.y);
                FFMA2(o01, ay2p, v.x);
                FFMA2(o23, ay2p, v.y);
            }
            unsigned int u0, u1, u2, u3;
            UNPACK2(u0, u1, o01);
            UNPACK2(u2, u3, o23);
            __half2 h0 = __floats2half2_rn(fmaxf(__uint_as_float(u0), 0.f),
                                           fmaxf(__uint_as_float(u1), 0.f));
            __half2 h1 = __floats2half2_rn(fmaxf(__uint_as_float(u2), 0.f),
                                           fmaxf(__uint_as_float(u3), 0.f));
            uint2 st;
            st.x = *reinterpret_cast<unsigned int*>(&h0);
            st.y = *reinterpret_cast<unsigned int*>(&h1);
            ((uint2*)(g_h3 + (size_t)nA * 64))[lane] = st;
        }
        // GEMV + store for node B
        if (hasB) {
            ulonglong2 bb = ((const ulonglong2*)sb)[lane];
            unsigned long long o01 = bb.x, o23 = bb.y;
#pragma unroll
            for (int k = 0; k < 32; k++) {
                float axk = __shfl_sync(0xffffffffu, accxB, k);
                float ayk = __shfl_sync(0xffffffffu, accyB, k);
                unsigned long long ax2p, ay2p;
                PACK_DUP(ax2p, axk);
                PACK_DUP(ay2p, ayk);
                ulonglong2 u = sWq[(2 * k) * 32 + lane];
                ulonglong2 v = sWq[(2 * k + 1) * 32 + lane];
                FFMA2(o01, ax2p, u.x);
                FFMA2(o23, ax2p, u.y);
                FFMA2(o01, ay2p, v.x);
                FFMA2(o23, ay2p, v.y);
            }
            unsigned int u0, u1, u2, u3;
            UNPACK2(u0, u1, o01);
            UNPACK2(u2, u3, o23);
            __half2 h0 = __floats2half2_rn(fmaxf(__uint_as_float(u0), 0.f),
                                           fmaxf(__uint_as_float(u1), 0.f));
            __half2 h1 = __floats2half2_rn(fmaxf(__uint_as_float(u2), 0.f),
                                           fmaxf(__uint_as_float(u3), 0.f));
            uint2 st;
            st.x = *reinterpret_cast<unsigned int*>(&h0);
            st.y = *reinterpret_cast<unsigned int*>(&h1);
            ((uint2*)(g_h3 + (size_t)nB * 64))[lane] = st;
        }
    }
}

// ============================================================
// Pool (mean; batch sorted) + MLP head. 64 threads per graph.
// ============================================================
__device__ __forceinline__ int lb_idx(const void* b, int n, int v, int is64) {
    int lo = 0, hi = n;
    while (lo < hi) {
        int m = (lo + hi) >> 1;
        if (idx_at(b, m, is64) < v) lo = m + 1; else hi = m;
    }
    return lo;
}

__global__ void k_poolhead(const void* __restrict__ batch, int N,
                           const float* __restrict__ Wf1, const float* __restrict__ bf1,
                           const float* __restrict__ Wf2, const float* __restrict__ bf2,
                           float* __restrict__ out) {
    __shared__ float sp[128];
    __shared__ float sz[32];
    int g = blockIdx.x;
    int t = threadIdx.x;   // 0..63, owns half2 feature pair t
    int is64 = g_is64;
    int lo = lb_idx(batch, N, g, is64);
    int hi = lb_idx(batch, N, g + 1, is64);
    float ax = 0.f, ay = 0.f;
    int i = lo;
    for (; i + 2 <= hi; i += 2) {
        float2 f0 = __half22float2(g_h3[(size_t)(i + 0) * 64 + t]);
        float2 f1 = __half22float2(g_h3[(size_t)(i + 1) * 64 + t]);
        ax += f0.x + f1.x;
        ay += f0.y + f1.y;
    }
    if (i < hi) {
        float2 f = __half22float2(g_h3[(size_t)i * 64 + t]);
        ax += f.x; ay += f.y;
    }
    float inv = 1.0f / fmaxf((float)(hi - lo), 1.0f);
    sp[2 * t]     = ax * inv;
    sp[2 * t + 1] = ay * inv;
    __syncthreads();
    if (t < 32) {
        float z = __ldg(&bf1[t]);
#pragma unroll 8
        for (int k = 0; k < 128; k++) z += sp[k] * __ldg(&Wf1[k * 32 + t]);
        sz[t] = fmaxf(z, 0.f);
    }
    __syncthreads();
    if (t < 4) {
        float o = __ldg(&bf2[t]);
#pragma unroll
        for (int k = 0; k < 32; k++) o += sz[k] * __ldg(&Wf2[k * 4 + t]);
        out[g * 4 + t] = o;
    }
}

// ============================================================
extern "C" void kernel_launch(void* const* d_in, const int* in_sizes, int n_in,
                              void* d_out, int out_size) {
    const float* x     = (const float*)d_in[0];
    const void*  ei    = d_in[1];
    const void*  batch = d_in[2];
    const float* W1 = (const float*)d_in[3];  const float* b1 = (const float*)d_in[4];
    const float* W2 = (const float*)d_in[5];  const float* b2 = (const float*)d_in[6];
    const float* W3 = (const float*)d_in[7];  const float* b3 = (const float*)d_in[8];
    const float* Wf1 = (const float*)d_in[9];  const float* bf1 = (const float*)d_in[10];
    const float* Wf2 = (const float*)d_in[11]; const float* bf2 = (const float*)d_in[12];
    float* out = (float*)d_out;

    int N = in_sizes[0] / 3;
    int E = in_sizes[1] / 2;
    int G = out_size / 4;

    k_prep<<<(N + 255) / 256, 256>>>((const int*)ei, E, N);
    k_fill<<<(E + 255) / 256, 256>>>(ei, E, N);
    k_scale<<<(N + 255) / 256, 256>>>(x, N);

    k_layer1<<<888, 256>>>(W1, b1, N);      // quad-node interleave
    k_layer2<<<444, 512>>>(W2, b2, N);      // dual-node gather, bounded regs
    k_layer3<<<444, 512>>>(W3, b3, N);      // dual-node gather, bounded regs

    k_poolhead<<<G, 64>>>(batch, N, Wf1, bf1, Wf2, bf2, out);
}

// round 14
// speedup vs baseline: 2.1997x; 2.1997x over previous
#include <cuda_runtime.h>
#include <cuda_fp16.h>
#include <math.h>

// Problem dims (fixed by the reference): N=50000, E=800000, G=512.
#define NMAX 50048
#define GMAX 512
#define MAXD 96     // per-node bucket capacity; deg ~ Poisson(16), P(>=96) ~ 0

// ---- packed fp32x2 helpers (sm_103a FFMA2; exact fp32) ----
#define FFMA2(d, a, b) \
    asm("fma.rn.f32x2 %0, %1, %2, %0;" : "+l"(d) : "l"(a), "l"(b))
#define PACK_DUP(d, x) \
    asm("mov.b64 %0, {%1, %1};" : "=l"(d) : "r"(__float_as_uint(x)))
#define UNPACK2(lo, hi, d) \
    asm("mov.b64 {%0, %1}, %2;" : "=r"(lo), "=r"(hi) : "l"(d))

// ---- scratch (device globals; no allocation allowed) ----
__device__ int     g_is64;               // 1 if index buffers are int64
__device__ int     g_deg[NMAX];
__device__ float   g_dinv[NMAX];
__device__ float4  g_px[NMAX];           // dinv[u] * x[u] padded to float4 (w=0)
__device__ int     g_slot[NMAX * MAXD];  // bucketed CSR-by-dst (src only)
__device__ __half2 g_ps1[NMAX * 16];     // dinv[u] * relu(h1[u])  (32 fp16)
__device__ __half2 g_ps2[NMAX * 32];     // dinv[u] * relu(h2[u])  (64 fp16)
__device__ __half2 g_h3[NMAX * 64];      // relu(h3[u])            (128 fp16)

__device__ __forceinline__ int idx_at(const void* p, long long i, int is64) {
    if (is64) return (int)((const long long*)p)[i];
    return ((const int*)p)[i];
}
__device__ __forceinline__ int clampi(int v, int lo, int hi) {
    return v < lo ? lo : (v > hi ? hi : v);
}

// ============================================================
// 0) zero degrees + detect index dtype
// ============================================================
__global__ void k_prep(const int* __restrict__ ebuf, int E, int N) {
    int i = blockIdx.x * blockDim.x + threadIdx.x;
    if (i < N) g_deg[i] = 0;
    if (blockIdx.x == 0) {
        __shared__ int s_nz;
        if (threadIdx.x == 0) s_nz = 0;
        __syncthreads();
        int nz = 0;
        int stride = (2 * E) / 4096;
        for (int k = threadIdx.x; k < 4096; k += blockDim.x) {
            long long w = (long long)k * stride | 1LL;
            if (w < 2LL * E) nz |= (ebuf[w] != 0);
        }
        if (nz) atomicOr(&s_nz, 1);
        __syncthreads();
        if (threadIdx.x == 0) g_is64 = (s_nz == 0) ? 1 : 0;
    }
}

// 1) bucket scatter: count + fill in ONE pass. Two edges per thread,
//    independent atomic->store chains (halve exposed latency).
__global__ void k_fill(const void* __restrict__ ei, int E, int N) {
    int half = (E + 1) >> 1;
    int e0 = blockIdx.x * blockDim.x + threadIdx.x;
    int e1 = e0 + half;
    int is64 = g_is64;
    if (e0 < E) {
        int s0 = clampi(idx_at(ei, e0, is64), 0, N - 1);
        int d0 = clampi(idx_at(ei, (long long)E + e0, is64), 0, N - 1);
        int s1 = 0, d1 = 0;
        bool has1 = (e1 < E);
        if (has1) {
            s1 = clampi(idx_at(ei, e1, is64), 0, N - 1);
            d1 = clampi(idx_at(ei, (long long)E + e1, is64), 0, N - 1);
        }
        int c0 = atomicAdd(&g_deg[d0], 1);
        int c1 = has1 ? atomicAdd(&g_deg[d1], 1) : MAXD;
        if (c0 < MAXD) g_slot[d0 * MAXD + c0] = s0;
        if (has1 && c1 < MAXD) g_slot[d1 * MAXD + c1] = s1;
    }
}

// 2) dinv = rsqrt(deg+1); pre-scale node features into float4
__global__ void k_scale(const float* __restrict__ x, int N) {
    int i = blockIdx.x * blockDim.x + threadIdx.x;
    if (i < N) {
        float di = rsqrtf((float)g_deg[i] + 1.0f);  // +1 self-loop
        g_dinv[i] = di;
        g_px[i] = make_float4(di * x[i * 3], di * x[i * 3 + 1], di * x[i * 3 + 2], 0.f);
    }
}

// ============================================================
// Layer 1: agg(3) @ W1(3x32) + b1, relu, pre-scale -> g_ps1 (fp16)
// TWO nodes per warp iteration (R12 measured best: 14.0us).
// ============================================================
__global__ void __launch_bounds__(256) k_layer1(const float* __restrict__ W1,
                                                const float* __restrict__ b1, int N) {
    __shared__ float sW[96];
    __shared__ float sb[32];
    int t = threadIdx.x;
    if (t < 96) sW[t] = W1[t];
    if (t < 32) sb[t] = b1[t];
    __syncthreads();
    int lane = t & 31;
    int warp0 = (blockIdx.x * blockDim.x + t) >> 5;
    int nwarps = (gridDim.x * blockDim.x) >> 5;
    int npairs = (N + 1) >> 1;
    for (int pr = warp0; pr < npairs; pr += nwarps) {
        int nA = 2 * pr;
        int nB = nA + 1;
        bool hasB = (nB < N);
        int degA = min(g_deg[nA], MAXD);
        int degB = hasB ? min(g_deg[nB], MAXD) : 0;
        int baseA = nA * MAXD, baseB = nB * MAXD;
        float axA = 0.f, ayA = 0.f, azA = 0.f;
        float axB = 0.f, ayB = 0.f, azB = 0.f;
        int dmax = max(degA, degB);
        for (int j = lane; j < dmax; j += 32) {
            if (j < degA) {
                float4 p = g_px[g_slot[baseA + j]];
                axA += p.x; ayA += p.y; azA += p.z;
            }
            if (j < degB) {
                float4 p = g_px[g_slot[baseB + j]];
                axB += p.x; ayB += p.y; azB += p.z;
            }
        }
#pragma unroll
        for (int st = 16; st >= 1; st >>= 1) {
            axA += __shfl_xor_sync(0xffffffffu, axA, st);
            ayA += __shfl_xor_sync(0xffffffffu, ayA, st);
            azA += __shfl_xor_sync(0xffffffffu, azA, st);
            axB += __shfl_xor_sync(0xffffffffu, axB, st);
            ayB += __shfl_xor_sync(0xffffffffu, ayB, st);
            azB += __shfl_xor_sync(0xffffffffu, azB, st);
        }
        float diA = g_dinv[nA];
        float4 selfA = g_px[nA];
        float a0 = diA * (axA + selfA.x);
        float a1 = diA * (ayA + selfA.y);
        float a2 = diA * (azA + selfA.z);
        float diB = 0.f, b0 = 0.f, b1v = 0.f, b2 = 0.f;
        if (hasB) {
            diB = g_dinv[nB];
            float4 selfB = g_px[nB];
            b0 = diB * (axB + selfB.x);
            b1v = diB * (ayB + selfB.y);
            b2 = diB * (azB + selfB.z);
        }
        if (lane < 16) {
            int f = 2 * lane;
            float w0 = sW[f],     w1 = sW[32 + f],     w2 = sW[64 + f];
            float v0 = sW[f + 1], v1 = sW[32 + f + 1], v2 = sW[64 + f + 1];
            float bb0 = sb[f], bb1 = sb[f + 1];
            float oA0 = bb0 + a0 * w0 + a1 * w1 + a2 * w2;
            float oA1 = bb1 + a0 * v0 + a1 * v1 + a2 * v2;
            g_ps1[nA * 16 + lane] =
                __floats2half2_rn(diA * fmaxf(oA0, 0.f), diA * fmaxf(oA1, 0.f));
            if (hasB) {
                float oB0 = bb0 + b0 * w0 + b1v * w1 + b2 * w2;
                float oB1 = bb1 + b0 * v0 + b1v * v1 + b2 * v2;
                g_ps1[nB * 16 + lane] =
                    __floats2half2_rn(diB * fmaxf(oB0, 0.f), diB * fmaxf(oB1, 0.f));
            }
        }
    }
}

// ============================================================
// Layer 2: agg(32) @ W2(32x64) + b2, relu, pre-scale -> g_ps2 (fp16)
// Single node/warp, NO launch bounds (R12 config); FFMA2 GEMV.
// ============================================================
__global__ void k_layer2(const float* __restrict__ W2,
                         const float* __restrict__ b2, int N) {
    __shared__ __align__(16) float sW[32 * 64];   // 8 KB
    __shared__ __align__(16) float sb[64];
    int t = threadIdx.x;
    for (int i = t; i < 32 * 64; i += blockDim.x) sW[i] = W2[i];
    if (t < 64) sb[t] = b2[t];
    __syncthreads();
    int lane = t & 31;
    int warp0 = (blockIdx.x * blockDim.x + t) >> 5;
    int nwarps = (gridDim.x * blockDim.x) >> 5;
    int q = lane & 15, p = lane >> 4;
    const unsigned long long* sWp = (const unsigned long long*)sW;
    for (int node = warp0; node < N; node += nwarps) {
        int deg = min(g_deg[node], MAXD);
        int base = node * MAXD;
        float di = g_dinv[node];
        float ax0 = 0.f, ay0 = 0.f, ax1 = 0.f, ay1 = 0.f;
        int j = p;
        for (; j + 2 < deg; j += 4) {
            int s0 = g_slot[base + j];
            int s1 = g_slot[base + j + 2];
            float2 f0 = __half22float2(g_ps1[(size_t)s0 * 16 + q]);
            float2 f1 = __half22float2(g_ps1[(size_t)s1 * 16 + q]);
            ax0 += f0.x; ay0 += f0.y;
            ax1 += f1.x; ay1 += f1.y;
        }
        if (j < deg) {
            int s = g_slot[base + j];
            float2 f = __half22float2(g_ps1[(size_t)s * 16 + q]);
            ax0 += f.x; ay0 += f.y;
        }
        float ax = ax0 + ax1, ay = ay0 + ay1;
        ax += __shfl_xor_sync(0xffffffffu, ax, 16);
        ay += __shfl_xor_sync(0xffffffffu, ay, 16);
        float2 self = __half22float2(g_ps1[(size_t)node * 16 + q]);
        float accx = di * (ax + self.x);   // input feature 2q
        float accy = di * (ay + self.y);   // input feature 2q+1
        unsigned long long o = ((const unsigned long long*)sb)[lane];
#pragma unroll
        for (int k = 0; k < 16; k++) {
            float axk = __shfl_sync(0xffffffffu, accx, k);
            float ayk = __shfl_sync(0xffffffffu, accy, k);
            unsigned long long ax2, ay2;
            PACK_DUP(ax2, axk);
            PACK_DUP(ay2, ayk);
            FFMA2(o, ax2, sWp[(2 * k) * 32 + lane]);
            FFMA2(o, ay2, sWp[(2 * k + 1) * 32 + lane]);
        }
        unsigned int u0, u1;
        UNPACK2(u0, u1, o);
        g_ps2[(size_t)node * 32 + lane] = __floats2half2_rn(
            di * fmaxf(__uint_as_float(u0), 0.f),
            di * fmaxf(__uint_as_float(u1), 0.f));
    }
}

// ============================================================
// Layer 3: agg(64 = one 128B row) @ W3(64x128) + b3, relu -> g_h3 (fp16)
// Single node/warp, NO launch bounds (R12 config); x4 gather; FFMA2 GEMV.
// ============================================================
__global__ void k_layer3(const float* __restrict__ W3,
                         const float* __restrict__ b3, int N) {
    __shared__ __align__(16) float sW[64 * 128];  // 32 KB
    __shared__ __align__(16) float sb[128];
    int t = threadIdx.x;
    for (int i = t; i < 64 * 128; i += blockDim.x) sW[i] = W3[i];
    if (t < 128) sb[t] = b3[t];
    __syncthreads();
    int lane = t & 31;
    int warp0 = (blockIdx.x * blockDim.x + t) >> 5;
    int nwarps = (gridDim.x * blockDim.x) >> 5;
    const ulonglong2* sWq = (const ulonglong2*)sW;
    for (int node = warp0; node < N; node += nwarps) {
        int deg = min(g_deg[node], MAXD);
        int base = node * MAXD;
        float di = g_dinv[node];
        float ax0 = 0.f, ay0 = 0.f, ax1 = 0.f, ay1 = 0.f;
        float ax2 = 0.f, ay2 = 0.f, ax3 = 0.f, ay3 = 0.f;
        int j = 0;
        for (; j + 4 <= deg; j += 4) {
            int s0 = g_slot[base + j];
            int s1 = g_slot[base + j + 1];
            int s2 = g_slot[base + j + 2];
            int s3 = g_slot[base + j + 3];
            float2 f0 = __half22float2(g_ps2[(size_t)s0 * 32 + lane]);
            float2 f1 = __half22float2(g_ps2[(size_t)s1 * 32 + lane]);
            float2 f2 = __half22float2(g_ps2[(size_t)s2 * 32 + lane]);
            float2 f3 = __half22float2(g_ps2[(size_t)s3 * 32 + lane]);
            ax0 += f0.x; ay0 += f0.y;
            ax1 += f1.x; ay1 += f1.y;
            ax2 += f2.x; ay2 += f2.y;
            ax3 += f3.x; ay3 += f3.y;
        }
        for (; j < deg; j++) {
            int s = g_slot[base + j];
            float2 f = __half22float2(g_ps2[(size_t)s * 32 + lane]);
            ax0 += f.x; ay0 += f.y;
        }
        float2 self = __half22float2(g_ps2[(size_t)node * 32 + lane]);
        float accx = di * (((ax0 + ax1) + (ax2 + ax3)) + self.x);
        float accy = di * (((ay0 + ay1) + (ay2 + ay3)) + self.y);
        unsigned long long o01, o23;   // outputs 4l..4l+3
        {
            ulonglong2 bb = ((const ulonglong2*)sb)[lane];
            o01 = bb.x; o23 = bb.y;
        }
#pragma unroll
        for (int k = 0; k < 32; k++) {
            float axk = __shfl_sync(0xffffffffu, accx, k);
            float ayk = __shfl_sync(0xffffffffu, accy, k);
            unsigned long long ax2p, ay2p;
            PACK_DUP(ax2p, axk);
            PACK_DUP(ay2p, ayk);
            ulonglong2 u = sWq[(2 * k) * 32 + lane];     // W3[2k][4l..4l+3]
            ulonglong2 v = sWq[(2 * k + 1) * 32 + lane]; // W3[2k+1][4l..4l+3]
            FFMA2(o01, ax2p, u.x);
            FFMA2(o23, ax2p, u.y);
            FFMA2(o01, ay2p, v.x);
            FFMA2(o23, ay2p, v.y);
        }
        unsigned int u0, u1, u2, u3;
        UNPACK2(u0, u1, o01);
        UNPACK2(u2, u3, o23);
        __half2 h0 = __floats2half2_rn(fmaxf(__uint_as_float(u0), 0.f),
                                       fmaxf(__uint_as_float(u1), 0.f));
        __half2 h1 = __floats2half2_rn(fmaxf(__uint_as_float(u2), 0.f),
                                       fmaxf(__uint_as_float(u3), 0.f));
        uint2 st;
        st.x = *reinterpret_cast<unsigned int*>(&h0);
        st.y = *reinterpret_cast<unsigned int*>(&h1);
        ((uint2*)(g_h3 + (size_t)node * 64))[lane] = st;
    }
}

// ============================================================
// Pool (mean; batch sorted) + MLP head. 64 threads per graph.
// ============================================================
__device__ __forceinline__ int lb_idx(const void* b, int n, int v, int is64) {
    int lo = 0, hi = n;
    while (lo < hi) {
        int m = (lo + hi) >> 1;
        if (idx_at(b, m, is64) < v) lo = m + 1; else hi = m;
    }
    return lo;
}

__global__ void k_poolhead(const void* __restrict__ batch, int N,
                           const float* __restrict__ Wf1, const float* __restrict__ bf1,
                           const float* __restrict__ Wf2, const float* __restrict__ bf2,
                           float* __restrict__ out) {
    __shared__ float sp[128];
    __shared__ float sz[32];
    int g = blockIdx.x;
    int t = threadIdx.x;   // 0..63, owns half2 feature pair t
    int is64 = g_is64;
    int lo = lb_idx(batch, N, g, is64);
    int hi = lb_idx(batch, N, g + 1, is64);
    float ax = 0.f, ay = 0.f;
    int i = lo;
    for (; i + 2 <= hi; i += 2) {
        float2 f0 = __half22float2(g_h3[(size_t)(i + 0) * 64 + t]);
        float2 f1 = __half22float2(g_h3[(size_t)(i + 1) * 64 + t]);
        ax += f0.x + f1.x;
        ay += f0.y + f1.y;
    }
    if (i < hi) {
        float2 f = __half22float2(g_h3[(size_t)i * 64 + t]);
        ax += f.x; ay += f.y;
    }
    float inv = 1.0f / fmaxf((float)(hi - lo), 1.0f);
    sp[2 * t]     = ax * inv;
    sp[2 * t + 1] = ay * inv;
    __syncthreads();
    if (t < 32) {
        float z = __ldg(&bf1[t]);
#pragma unroll 8
        for (int k = 0; k < 128; k++) z += sp[k] * __ldg(&Wf1[k * 32 + t]);
        sz[t] = fmaxf(z, 0.f);
    }
    __syncthreads();
    if (t < 4) {
        float o = __ldg(&bf2[t]);
#pragma unroll
        for (int k = 0; k < 32; k++) o += sz[k] * __ldg(&Wf2[k * 4 + t]);
        out[g * 4 + t] = o;
    }
}

// ============================================================
extern "C" void kernel_launch(void* const* d_in, const int* in_sizes, int n_in,
                              void* d_out, int out_size) {
    const float* x     = (const float*)d_in[0];
    const void*  ei    = d_in[1];
    const void*  batch = d_in[2];
    const float* W1 = (const float*)d_in[3];  const float* b1 = (const float*)d_in[4];
    const float* W2 = (const float*)d_in[5];  const float* b2 = (const float*)d_in[6];
    const float* W3 = (const float*)d_in[7];  const float* b3 = (const float*)d_in[8];
    const float* Wf1 = (const float*)d_in[9];  const float* bf1 = (const float*)d_in[10];
    const float* Wf2 = (const float*)d_in[11]; const float* bf2 = (const float*)d_in[12];
    float* out = (float*)d_out;

    int N = in_sizes[0] / 3;
    int E = in_sizes[1] / 2;
    int G = out_size / 4;

    int ehalf = (E + 1) >> 1;
    k_prep<<<(N + 255) / 256, 256>>>((const int*)ei, E, N);
    k_fill<<<(ehalf + 255) / 256, 256>>>(ei, E, N);
    k_scale<<<(N + 255) / 256, 256>>>(x, N);

    k_layer1<<<888, 256>>>(W1, b1, N);      // dual-node (R12 measured best)
    k_layer2<<<444, 512>>>(W2, b2, N);      // R12 single-node config
    k_layer3<<<444, 512>>>(W3, b3, N);      // R12 single-node config

    k_poolhead<<<G, 64>>>(batch, N, Wf1, bf1, Wf2, bf2, out);
}

// round 15
// speedup vs baseline: 2.5152x; 1.1434x over previous
#include <cuda_runtime.h>
#include <cuda_fp16.h>
#include <math.h>

// Problem dims (fixed by the reference): N=50000, E=800000, G=512.
#define NMAX 50048
#define GMAX 512
#define MAXD 96     // per-node bucket capacity; deg ~ Poisson(16), P(>=96) ~ 0

// ---- packed fp32x2 helpers (sm_103a FFMA2; exact fp32) ----
#define FFMA2(d, a, b) \
    asm("fma.rn.f32x2 %0, %1, %2, %0;" : "+l"(d) : "l"(a), "l"(b))
#define PACK_DUP(d, x) \
    asm("mov.b64 %0, {%1, %1};" : "=l"(d) : "r"(__float_as_uint(x)))
#define UNPACK2(lo, hi, d) \
    asm("mov.b64 {%0, %1}, %2;" : "=r"(lo), "=r"(hi) : "l"(d))

// ---- scratch (device globals; no allocation allowed) ----
__device__ int     g_is64;               // 1 if index buffers are int64
__device__ int     g_deg[NMAX];
__device__ float   g_dinv[NMAX];
__device__ float4  g_px[NMAX];           // dinv[u] * x[u] padded to float4 (w=0)
__device__ int     g_slot[NMAX * MAXD];  // bucketed CSR-by-dst (src only)
__device__ __half2 g_ps1[NMAX * 16];     // dinv[u] * relu(h1[u])  (32 fp16)
__device__ __half2 g_ps2[NMAX * 32];     // dinv[u] * relu(h2[u])  (64 fp16)
__device__ __half2 g_h3[NMAX * 64];      // relu(h3[u])            (128 fp16)

__device__ __forceinline__ int idx_at(const void* p, long long i, int is64) {
    if (is64) return (int)((const long long*)p)[i];
    return ((const int*)p)[i];
}
__device__ __forceinline__ int clampi(int v, int lo, int hi) {
    return v < lo ? lo : (v > hi ? hi : v);
}

// ============================================================
// 0) zero degrees + detect index dtype
// ============================================================
__global__ void k_prep(const int* __restrict__ ebuf, int E, int N) {
    int i = blockIdx.x * blockDim.x + threadIdx.x;
    if (i < N) g_deg[i] = 0;
    if (blockIdx.x == 0) {
        __shared__ int s_nz;
        if (threadIdx.x == 0) s_nz = 0;
        __syncthreads();
        int nz = 0;
        int stride = (2 * E) / 4096;
        for (int k = threadIdx.x; k < 4096; k += blockDim.x) {
            long long w = (long long)k * stride | 1LL;
            if (w < 2LL * E) nz |= (ebuf[w] != 0);
        }
        if (nz) atomicOr(&s_nz, 1);
        __syncthreads();
        if (threadIdx.x == 0) g_is64 = (s_nz == 0) ? 1 : 0;
    }
}

// 1) bucket scatter: count + fill in ONE pass (R12 single-edge order)
__global__ void k_fill(const void* __restrict__ ei, int E, int N) {
    int e = blockIdx.x * blockDim.x + threadIdx.x;
    if (e < E) {
        int is64 = g_is64;
        int s = clampi(idx_at(ei, e, is64), 0, N - 1);
        int d = clampi(idx_at(ei, (long long)E + e, is64), 0, N - 1);
        int c = atomicAdd(&g_deg[d], 1);
        if (c < MAXD) g_slot[d * MAXD + c] = s;
    }
}

// 2) dinv = rsqrt(deg+1); pre-scale node features into float4
__global__ void k_scale(const float* __restrict__ x, int N) {
    int i = blockIdx.x * blockDim.x + threadIdx.x;
    if (i < N) {
        float di = rsqrtf((float)g_deg[i] + 1.0f);  // +1 self-loop
        g_dinv[i] = di;
        g_px[i] = make_float4(di * x[i * 3], di * x[i * 3 + 1], di * x[i * 3 + 2], 0.f);
    }
}

// ============================================================
// Layer 1: agg(3) @ W1(3x32) + b1, relu, pre-scale -> g_ps1 (fp16)
// TWO nodes per warp iteration (R12 measured best: 14.0us).
// ============================================================
__global__ void __launch_bounds__(256) k_layer1(const float* __restrict__ W1,
                                                const float* __restrict__ b1, int N) {
    __shared__ float sW[96];
    __shared__ float sb[32];
    int t = threadIdx.x;
    if (t < 96) sW[t] = W1[t];
    if (t < 32) sb[t] = b1[t];
    __syncthreads();
    int lane = t & 31;
    int warp0 = (blockIdx.x * blockDim.x + t) >> 5;
    int nwarps = (gridDim.x * blockDim.x) >> 5;
    int npairs = (N + 1) >> 1;
    for (int pr = warp0; pr < npairs; pr += nwarps) {
        int nA = 2 * pr;
        int nB = nA + 1;
        bool hasB = (nB < N);
        int degA = min(g_deg[nA], MAXD);
        int degB = hasB ? min(g_deg[nB], MAXD) : 0;
        int baseA = nA * MAXD, baseB = nB * MAXD;
        float axA = 0.f, ayA = 0.f, azA = 0.f;
        float axB = 0.f, ayB = 0.f, azB = 0.f;
        int dmax = max(degA, degB);
        for (int j = lane; j < dmax; j += 32) {
            if (j < degA) {
                float4 p = g_px[g_slot[baseA + j]];
                axA += p.x; ayA += p.y; azA += p.z;
            }
            if (j < degB) {
                float4 p = g_px[g_slot[baseB + j]];
                axB += p.x; ayB += p.y; azB += p.z;
            }
        }
#pragma unroll
        for (int st = 16; st >= 1; st >>= 1) {
            axA += __shfl_xor_sync(0xffffffffu, axA, st);
            ayA += __shfl_xor_sync(0xffffffffu, ayA, st);
            azA += __shfl_xor_sync(0xffffffffu, azA, st);
            axB += __shfl_xor_sync(0xffffffffu, axB, st);
            ayB += __shfl_xor_sync(0xffffffffu, ayB, st);
            azB += __shfl_xor_sync(0xffffffffu, azB, st);
        }
        float diA = g_dinv[nA];
        float4 selfA = g_px[nA];
        float a0 = diA * (axA + selfA.x);
        float a1 = diA * (ayA + selfA.y);
        float a2 = diA * (azA + selfA.z);
        float diB = 0.f, b0 = 0.f, b1v = 0.f, b2 = 0.f;
        if (hasB) {
            diB = g_dinv[nB];
            float4 selfB = g_px[nB];
            b0 = diB * (axB + selfB.x);
            b1v = diB * (ayB + selfB.y);
            b2 = diB * (azB + selfB.z);
        }
        if (lane < 16) {
            int f = 2 * lane;
            float w0 = sW[f],     w1 = sW[32 + f],     w2 = sW[64 + f];
            float v0 = sW[f + 1], v1 = sW[32 + f + 1], v2 = sW[64 + f + 1];
            float bb0 = sb[f], bb1 = sb[f + 1];
            float oA0 = bb0 + a0 * w0 + a1 * w1 + a2 * w2;
            float oA1 = bb1 + a0 * v0 + a1 * v1 + a2 * v2;
            g_ps1[nA * 16 + lane] =
                __floats2half2_rn(diA * fmaxf(oA0, 0.f), diA * fmaxf(oA1, 0.f));
            if (hasB) {
                float oB0 = bb0 + b0 * w0 + b1v * w1 + b2 * w2;
                float oB1 = bb1 + b0 * v0 + b1v * v1 + b2 * v2;
                g_ps1[nB * 16 + lane] =
                    __floats2half2_rn(diB * fmaxf(oB0, 0.f), diB * fmaxf(oB1, 0.f));
            }
        }
    }
}

// ============================================================
// Layer 2: agg(32) @ W2(32x64) + b2, relu, pre-scale -> g_ps2 (fp16)
// Dual-node, SHARED-WEIGHT interleaved GEMV (each LDS feeds both nodes:
// halves smem crossbar traffic). Gather: half-warp edge split per node.
// ============================================================
__global__ void k_layer2(const float* __restrict__ W2,
                         const float* __restrict__ b2, int N) {
    __shared__ __align__(16) float sW[32 * 64];   // 8 KB
    __shared__ __align__(16) float sb[64];
    int t = threadIdx.x;
    for (int i = t; i < 32 * 64; i += blockDim.x) sW[i] = W2[i];
    if (t < 64) sb[t] = b2[t];
    __syncthreads();
    int lane = t & 31;
    int warp0 = (blockIdx.x * blockDim.x + t) >> 5;
    int nwarps = (gridDim.x * blockDim.x) >> 5;
    int q = lane & 15, p = lane >> 4;
    const unsigned long long* sWp = (const unsigned long long*)sW;
    int npairs = (N + 1) >> 1;
    for (int pr = warp0; pr < npairs; pr += nwarps) {
        int nA = 2 * pr;
        int nB = nA + 1;
        bool hasB = (nB < N);
        int degA = min(g_deg[nA], MAXD);
        int degB = hasB ? min(g_deg[nB], MAXD) : 0;
        int baseA = nA * MAXD, baseB = nB * MAXD;
        float axA = 0.f, ayA = 0.f, axB = 0.f, ayB = 0.f;
        int dmax = max(degA, degB);
        for (int j = p; j < dmax; j += 2) {
            if (j < degA) {
                float2 f = __half22float2(g_ps1[(size_t)g_slot[baseA + j] * 16 + q]);
                axA += f.x; ayA += f.y;
            }
            if (j < degB) {
                float2 f = __half22float2(g_ps1[(size_t)g_slot[baseB + j] * 16 + q]);
                axB += f.x; ayB += f.y;
            }
        }
        axA += __shfl_xor_sync(0xffffffffu, axA, 16);
        ayA += __shfl_xor_sync(0xffffffffu, ayA, 16);
        axB += __shfl_xor_sync(0xffffffffu, axB, 16);
        ayB += __shfl_xor_sync(0xffffffffu, ayB, 16);
        float diA = g_dinv[nA];
        float2 selfA = __half22float2(g_ps1[(size_t)nA * 16 + q]);
        float accxA = diA * (axA + selfA.x);
        float accyA = diA * (ayA + selfA.y);
        float diB = 0.f, accxB = 0.f, accyB = 0.f;
        if (hasB) {
            diB = g_dinv[nB];
            float2 selfB = __half22float2(g_ps1[(size_t)nB * 16 + q]);
            accxB = diB * (axB + selfB.x);
            accyB = diB * (ayB + selfB.y);
        }
        // Interleaved GEMV: one weight load feeds both nodes.
        unsigned long long oA = ((const unsigned long long*)sb)[lane];
        unsigned long long oB = oA;
#pragma unroll
        for (int k = 0; k < 16; k++) {
            float axkA = __shfl_sync(0xffffffffu, accxA, k);
            float aykA = __shfl_sync(0xffffffffu, accyA, k);
            float axkB = __shfl_sync(0xffffffffu, accxB, k);
            float aykB = __shfl_sync(0xffffffffu, accyB, k);
            unsigned long long dxA, dyA, dxB, dyB;
            PACK_DUP(dxA, axkA);
            PACK_DUP(dyA, aykA);
            PACK_DUP(dxB, axkB);
            PACK_DUP(dyB, aykB);
            unsigned long long w0 = sWp[(2 * k) * 32 + lane];
            unsigned long long w1 = sWp[(2 * k + 1) * 32 + lane];
            FFMA2(oA, dxA, w0);
            FFMA2(oA, dyA, w1);
            FFMA2(oB, dxB, w0);
            FFMA2(oB, dyB, w1);
        }
        unsigned int u0, u1;
        UNPACK2(u0, u1, oA);
        g_ps2[(size_t)nA * 32 + lane] = __floats2half2_rn(
            diA * fmaxf(__uint_as_float(u0), 0.f),
            diA * fmaxf(__uint_as_float(u1), 0.f));
        if (hasB) {
            UNPACK2(u0, u1, oB);
            g_ps2[(size_t)nB * 32 + lane] = __floats2half2_rn(
                diB * fmaxf(__uint_as_float(u0), 0.f),
                diB * fmaxf(__uint_as_float(u1), 0.f));
        }
    }
}

// ============================================================
// Layer 3: agg(64 = one 128B row) @ W3(64x128) + b3, relu -> g_h3 (fp16)
// Dual-node, SHARED-WEIGHT interleaved GEMV (halves smem traffic).
// ============================================================
__global__ void k_layer3(const float* __restrict__ W3,
                         const float* __restrict__ b3, int N) {
    __shared__ __align__(16) float sW[64 * 128];  // 32 KB
    __shared__ __align__(16) float sb[128];
    int t = threadIdx.x;
    for (int i = t; i < 64 * 128; i += blockDim.x) sW[i] = W3[i];
    if (t < 128) sb[t] = b3[t];
    __syncthreads();
    int lane = t & 31;
    int warp0 = (blockIdx.x * blockDim.x + t) >> 5;
    int nwarps = (gridDim.x * blockDim.x) >> 5;
    const ulonglong2* sWq = (const ulonglong2*)sW;
    int npairs = (N + 1) >> 1;
    for (int pr = warp0; pr < npairs; pr += nwarps) {
        int nA = 2 * pr;
        int nB = nA + 1;
        bool hasB = (nB < N);
        int degA = min(g_deg[nA], MAXD);
        int degB = hasB ? min(g_deg[nB], MAXD) : 0;
        int baseA = nA * MAXD, baseB = nB * MAXD;
        float axA = 0.f, ayA = 0.f, axB = 0.f, ayB = 0.f;
        int dmax = max(degA, degB);
        for (int j = 0; j < dmax; j++) {
            if (j < degA) {
                float2 f = __half22float2(g_ps2[(size_t)g_slot[baseA + j] * 32 + lane]);
                axA += f.x; ayA += f.y;
            }
            if (j < degB) {
                float2 f = __half22float2(g_ps2[(size_t)g_slot[baseB + j] * 32 + lane]);
                axB += f.x; ayB += f.y;
            }
        }
        float diA = g_dinv[nA];
        float2 selfA = __half22float2(g_ps2[(size_t)nA * 32 + lane]);
        float accxA = diA * (axA + selfA.x);
        float accyA = diA * (ayA + selfA.y);
        float diB = 0.f, accxB = 0.f, accyB = 0.f;
        if (hasB) {
            diB = g_dinv[nB];
            float2 selfB = __half22float2(g_ps2[(size_t)nB * 32 + lane]);
            accxB = diB * (axB + selfB.x);
            accyB = diB * (ayB + selfB.y);
        }
        // Interleaved GEMV: each ulonglong2 weight load feeds both nodes.
        unsigned long long o01A, o23A, o01B, o23B;
        {
            ulonglong2 bb = ((const ulonglong2*)sb)[lane];
            o01A = bb.x; o23A = bb.y;
            o01B = bb.x; o23B = bb.y;
        }
#pragma unroll
        for (int k = 0; k < 32; k++) {
            float axkA = __shfl_sync(0xffffffffu, accxA, k);
            float aykA = __shfl_sync(0xffffffffu, accyA, k);
            float axkB = __shfl_sync(0xffffffffu, accxB, k);
            float aykB = __shfl_sync(0xffffffffu, accyB, k);
            unsigned long long dxA, dyA, dxB, dyB;
            PACK_DUP(dxA, axkA);
            PACK_DUP(dyA, aykA);
            PACK_DUP(dxB, axkB);
            PACK_DUP(dyB, aykB);
            ulonglong2 u = sWq[(2 * k) * 32 + lane];     // W3[2k][4l..4l+3]
            ulonglong2 v = sWq[(2 * k + 1) * 32 + lane]; // W3[2k+1][4l..4l+3]
            FFMA2(o01A, dxA, u.x);
            FFMA2(o23A, dxA, u.y);
            FFMA2(o01A, dyA, v.x);
            FFMA2(o23A, dyA, v.y);
            FFMA2(o01B, dxB, u.x);
            FFMA2(o23B, dxB, u.y);
            FFMA2(o01B, dyB, v.x);
            FFMA2(o23B, dyB, v.y);
        }
        unsigned int u0, u1, u2, u3;
        UNPACK2(u0, u1, o01A);
        UNPACK2(u2, u3, o23A);
        {
            __half2 h0 = __floats2half2_rn(fmaxf(__uint_as_float(u0), 0.f),
                                           fmaxf(__uint_as_float(u1), 0.f));
            __half2 h1 = __floats2half2_rn(fmaxf(__uint_as_float(u2), 0.f),
                                           fmaxf(__uint_as_float(u3), 0.f));
            uint2 st;
            st.x = *reinterpret_cast<unsigned int*>(&h0);
            st.y = *reinterpret_cast<unsigned int*>(&h1);
            ((uint2*)(g_h3 + (size_t)nA * 64))[lane] = st;
        }
        if (hasB) {
            UNPACK2(u0, u1, o01B);
            UNPACK2(u2, u3, o23B);
            __half2 h0 = __floats2half2_rn(fmaxf(__uint_as_float(u0), 0.f),
                                           fmaxf(__uint_as_float(u1), 0.f));
            __half2 h1 = __floats2half2_rn(fmaxf(__uint_as_float(u2), 0.f),
                                           fmaxf(__uint_as_float(u3), 0.f));
            uint2 st;
            st.x = *reinterpret_cast<unsigned int*>(&h0);
            st.y = *reinterpret_cast<unsigned int*>(&h1);
            ((uint2*)(g_h3 + (size_t)nB * 64))[lane] = st;
        }
    }
}

// ============================================================
// Pool (mean; batch sorted) + MLP head. 64 threads per graph.
// ============================================================
__device__ __forceinline__ int lb_idx(const void* b, int n, int v, int is64) {
    int lo = 0, hi = n;
    while (lo < hi) {
        int m = (lo + hi) >> 1;
        if (idx_at(b, m, is64) < v) lo = m + 1; else hi = m;
    }
    return lo;
}

__global__ void k_poolhead(const void* __restrict__ batch, int N,
                           const float* __restrict__ Wf1, const float* __restrict__ bf1,
                           const float* __restrict__ Wf2, const float* __restrict__ bf2,
                           float* __restrict__ out) {
    __shared__ float sp[128];
    __shared__ float sz[32];
    int g = blockIdx.x;
    int t = threadIdx.x;   // 0..63, owns half2 feature pair t
    int is64 = g_is64;
    int lo = lb_idx(batch, N, g, is64);
    int hi = lb_idx(batch, N, g + 1, is64);
    float ax = 0.f, ay = 0.f;
    int i = lo;
    for (; i + 2 <= hi; i += 2) {
        float2 f0 = __half22float2(g_h3[(size_t)(i + 0) * 64 + t]);
        float2 f1 = __half22float2(g_h3[(size_t)(i + 1) * 64 + t]);
        ax += f0.x + f1.x;
        ay += f0.y + f1.y;
    }
    if (i < hi) {
        float2 f = __half22float2(g_h3[(size_t)i * 64 + t]);
        ax += f.x; ay += f.y;
    }
    float inv = 1.0f / fmaxf((float)(hi - lo), 1.0f);
    sp[2 * t]     = ax * inv;
    sp[2 * t + 1] = ay * inv;
    __syncthreads();
    if (t < 32) {
        float z = __ldg(&bf1[t]);
#pragma unroll 8
        for (int k = 0; k < 128; k++) z += sp[k] * __ldg(&Wf1[k * 32 + t]);
        sz[t] = fmaxf(z, 0.f);
    }
    __syncthreads();
    if (t < 4) {
        float o = __ldg(&bf2[t]);
#pragma unroll
        for (int k = 0; k < 32; k++) o += sz[k] * __ldg(&Wf2[k * 4 + t]);
        out[g * 4 + t] = o;
    }
}

// ============================================================
extern "C" void kernel_launch(void* const* d_in, const int* in_sizes, int n_in,
                              void* d_out, int out_size) {
    const float* x     = (const float*)d_in[0];
    const void*  ei    = d_in[1];
    const void*  batch = d_in[2];
    const float* W1 = (const float*)d_in[3];  const float* b1 = (const float*)d_in[4];
    const float* W2 = (const float*)d_in[5];  const float* b2 = (const float*)d_in[6];
    const float* W3 = (const float*)d_in[7];  const float* b3 = (const float*)d_in[8];
    const float* Wf1 = (const float*)d_in[9];  const float* bf1 = (const float*)d_in[10];
    const float* Wf2 = (const float*)d_in[11]; const float* bf2 = (const float*)d_in[12];
    float* out = (float*)d_out;

    int N = in_sizes[0] / 3;
    int E = in_sizes[1] / 2;
    int G = out_size / 4;

    k_prep<<<(N + 255) / 256, 256>>>((const int*)ei, E, N);
    k_fill<<<(E + 255) / 256, 256>>>(ei, E, N);
    k_scale<<<(N + 255) / 256, 256>>>(x, N);

    k_layer1<<<888, 256>>>(W1, b1, N);      // dual-node (R12 measured best)
    k_layer2<<<888, 256>>>(W2, b2, N);      // dual-node shared-weight GEMV
    k_layer3<<<888, 256>>>(W3, b3, N);      // dual-node shared-weight GEMV

    k_poolhead<<<G, 64>>>(batch, N, Wf1, bf1, Wf2, bf2, out);
}

// round 16
// speedup vs baseline: 2.6844x; 1.0673x over previous
#include <cuda_runtime.h>
#include <cuda_fp16.h>
#include <math.h>

// Problem dims (fixed by the reference): N=50000, E=800000, G=512.
#define NMAX 50048
#define GMAX 512
#define MAXD 96     // per-node bucket capacity; deg ~ Poisson(16), P(>=96) ~ 0

// ---- packed fp32x2 helpers (sm_103a FFMA2; exact fp32) ----
#define FFMA2(d, a, b) \
    asm("fma.rn.f32x2 %0, %1, %2, %0;" : "+l"(d) : "l"(a), "l"(b))
#define PACK_DUP(d, x) \
    asm("mov.b64 %0, {%1, %1};" : "=l"(d) : "r"(__float_as_uint(x)))
#define UNPACK2(lo, hi, d) \
    asm("mov.b64 {%0, %1}, %2;" : "=r"(lo), "=r"(hi) : "l"(d))

// ---- scratch (device globals; no allocation allowed) ----
__device__ int     g_is64;               // 1 if index buffers are int64
__device__ int     g_deg[NMAX];
__device__ float   g_dinv[NMAX];
__device__ float4  g_px[NMAX];           // dinv[u] * x[u] padded to float4 (w=0)
__device__ int     g_slot[NMAX * MAXD];  // bucketed CSR-by-dst (src only)
__device__ __half2 g_ps1[NMAX * 16];     // dinv[u] * relu(h1[u])  (32 fp16)
__device__ __half2 g_ps2[NMAX * 32];     // dinv[u] * relu(h2[u])  (64 fp16)
__device__ __half2 g_h3[NMAX * 64];      // relu(h3[u])            (128 fp16)

__device__ __forceinline__ int idx_at(const void* p, long long i, int is64) {
    if (is64) return (int)((const long long*)p)[i];
    return ((const int*)p)[i];
}
__device__ __forceinline__ int clampi(int v, int lo, int hi) {
    return v < lo ? lo : (v > hi ? hi : v);
}

// ============================================================
// 0) zero degrees + detect index dtype
// ============================================================
__global__ void k_prep(const int* __restrict__ ebuf, int E, int N) {
    int i = blockIdx.x * blockDim.x + threadIdx.x;
    if (i < N) g_deg[i] = 0;
    if (blockIdx.x == 0) {
        __shared__ int s_nz;
        if (threadIdx.x == 0) s_nz = 0;
        __syncthreads();
        int nz = 0;
        int stride = (2 * E) / 4096;
        for (int k = threadIdx.x; k < 4096; k += blockDim.x) {
            long long w = (long long)k * stride | 1LL;
            if (w < 2LL * E) nz |= (ebuf[w] != 0);
        }
        if (nz) atomicOr(&s_nz, 1);
        __syncthreads();
        if (threadIdx.x == 0) g_is64 = (s_nz == 0) ? 1 : 0;
    }
}

// 1) bucket scatter: count + fill in ONE pass
__global__ void k_fill(const void* __restrict__ ei, int E, int N) {
    int e = blockIdx.x * blockDim.x + threadIdx.x;
    if (e < E) {
        int is64 = g_is64;
        int s = clampi(idx_at(ei, e, is64), 0, N - 1);
        int d = clampi(idx_at(ei, (long long)E + e, is64), 0, N - 1);
        int c = atomicAdd(&g_deg[d], 1);
        if (c < MAXD) g_slot[d * MAXD + c] = s;
    }
}

// 2) dinv = rsqrt(deg+1); pre-scale node features into float4
__global__ void k_scale(const float* __restrict__ x, int N) {
    int i = blockIdx.x * blockDim.x + threadIdx.x;
    if (i < N) {
        float di = rsqrtf((float)g_deg[i] + 1.0f);  // +1 self-loop
        g_dinv[i] = di;
        g_px[i] = make_float4(di * x[i * 3], di * x[i * 3 + 1], di * x[i * 3 + 2], 0.f);
    }
}

// ============================================================
// Layer 1: agg(3) @ W1(3x32) + b1, relu, pre-scale -> g_ps1 (fp16)
// TWO nodes per warp iteration (R12/R15 measured best).
// ============================================================
__global__ void __launch_bounds__(256) k_layer1(const float* __restrict__ W1,
                                                const float* __restrict__ b1, int N) {
    __shared__ float sW[96];
    __shared__ float sb[32];
    int t = threadIdx.x;
    if (t < 96) sW[t] = W1[t];
    if (t < 32) sb[t] = b1[t];
    __syncthreads();
    int lane = t & 31;
    int warp0 = (blockIdx.x * blockDim.x + t) >> 5;
    int nwarps = (gridDim.x * blockDim.x) >> 5;
    int npairs = (N + 1) >> 1;
    for (int pr = warp0; pr < npairs; pr += nwarps) {
        int nA = 2 * pr;
        int nB = nA + 1;
        bool hasB = (nB < N);
        int degA = min(g_deg[nA], MAXD);
        int degB = hasB ? min(g_deg[nB], MAXD) : 0;
        int baseA = nA * MAXD, baseB = nB * MAXD;
        float axA = 0.f, ayA = 0.f, azA = 0.f;
        float axB = 0.f, ayB = 0.f, azB = 0.f;
        int dmax = max(degA, degB);
        for (int j = lane; j < dmax; j += 32) {
            if (j < degA) {
                float4 p = g_px[g_slot[baseA + j]];
                axA += p.x; ayA += p.y; azA += p.z;
            }
            if (j < degB) {
                float4 p = g_px[g_slot[baseB + j]];
                axB += p.x; ayB += p.y; azB += p.z;
            }
        }
#pragma unroll
        for (int st = 16; st >= 1; st >>= 1) {
            axA += __shfl_xor_sync(0xffffffffu, axA, st);
            ayA += __shfl_xor_sync(0xffffffffu, ayA, st);
            azA += __shfl_xor_sync(0xffffffffu, azA, st);
            axB += __shfl_xor_sync(0xffffffffu, axB, st);
            ayB += __shfl_xor_sync(0xffffffffu, ayB, st);
            azB += __shfl_xor_sync(0xffffffffu, azB, st);
        }
        float diA = g_dinv[nA];
        float4 selfA = g_px[nA];
        float a0 = diA * (axA + selfA.x);
        float a1 = diA * (ayA + selfA.y);
        float a2 = diA * (azA + selfA.z);
        float diB = 0.f, b0 = 0.f, b1v = 0.f, b2 = 0.f;
        if (hasB) {
            diB = g_dinv[nB];
            float4 selfB = g_px[nB];
            b0 = diB * (axB + selfB.x);
            b1v = diB * (ayB + selfB.y);
            b2 = diB * (azB + selfB.z);
        }
        if (lane < 16) {
            int f = 2 * lane;
            float w0 = sW[f],     w1 = sW[32 + f],     w2 = sW[64 + f];
            float v0 = sW[f + 1], v1 = sW[32 + f + 1], v2 = sW[64 + f + 1];
            float bb0 = sb[f], bb1 = sb[f + 1];
            float oA0 = bb0 + a0 * w0 + a1 * w1 + a2 * w2;
            float oA1 = bb1 + a0 * v0 + a1 * v1 + a2 * v2;
            g_ps1[nA * 16 + lane] =
                __floats2half2_rn(diA * fmaxf(oA0, 0.f), diA * fmaxf(oA1, 0.f));
            if (hasB) {
                float oB0 = bb0 + b0 * w0 + b1v * w1 + b2 * w2;
                float oB1 = bb1 + b0 * v0 + b1v * v1 + b2 * v2;
                g_ps1[nB * 16 + lane] =
                    __floats2half2_rn(diB * fmaxf(oB0, 0.f), diB * fmaxf(oB1, 0.f));
            }
        }
    }
}

// ============================================================
// Layer 2: agg(32) @ W2(32x64) + b2, relu, pre-scale -> g_ps2 (fp16)
// QUAD-node shared-weight GEMV: each weight LDS feeds 4 nodes.
// ============================================================
__global__ void k_layer2(const float* __restrict__ W2,
                         const float* __restrict__ b2, int N) {
    __shared__ __align__(16) float sW[32 * 64];   // 8 KB
    __shared__ __align__(16) float sb[64];
    int t = threadIdx.x;
    for (int i = t; i < 32 * 64; i += blockDim.x) sW[i] = W2[i];
    if (t < 64) sb[t] = b2[t];
    __syncthreads();
    int lane = t & 31;
    int warp0 = (blockIdx.x * blockDim.x + t) >> 5;
    int nwarps = (gridDim.x * blockDim.x) >> 5;
    int q = lane & 15, p = lane >> 4;
    const unsigned long long* sWp = (const unsigned long long*)sW;
    int nquads = (N + 3) >> 2;
    for (int qd = warp0; qd < nquads; qd += nwarps) {
        int n0 = 4 * qd;
        int deg[4], base[4];
        float ax[4], ay[4];
        int dmax = 0;
#pragma unroll
        for (int u = 0; u < 4; u++) {
            int nu = n0 + u;
            deg[u] = (nu < N) ? min(g_deg[nu], MAXD) : 0;
            base[u] = nu * MAXD;
            ax[u] = 0.f; ay[u] = 0.f;
            dmax = max(dmax, deg[u]);
        }
        for (int j = p; j < dmax; j += 2) {
#pragma unroll
            for (int u = 0; u < 4; u++) {
                if (j < deg[u]) {
                    float2 f = __half22float2(g_ps1[(size_t)g_slot[base[u] + j] * 16 + q]);
                    ax[u] += f.x; ay[u] += f.y;
                }
            }
        }
        float di[4], accx[4], accy[4];
#pragma unroll
        for (int u = 0; u < 4; u++) {
            ax[u] += __shfl_xor_sync(0xffffffffu, ax[u], 16);
            ay[u] += __shfl_xor_sync(0xffffffffu, ay[u], 16);
            int nu = n0 + u;
            if (nu < N) {
                di[u] = g_dinv[nu];
                float2 self = __half22float2(g_ps1[(size_t)nu * 16 + q]);
                accx[u] = di[u] * (ax[u] + self.x);
                accy[u] = di[u] * (ay[u] + self.y);
            } else {
                di[u] = 0.f; accx[u] = 0.f; accy[u] = 0.f;
            }
        }
        // Interleaved GEMV: one weight load feeds all 4 nodes.
        unsigned long long o[4];
        unsigned long long binit = ((const unsigned long long*)sb)[lane];
#pragma unroll
        for (int u = 0; u < 4; u++) o[u] = binit;
#pragma unroll
        for (int k = 0; k < 16; k++) {
            unsigned long long w0 = sWp[(2 * k) * 32 + lane];
            unsigned long long w1 = sWp[(2 * k + 1) * 32 + lane];
#pragma unroll
            for (int u = 0; u < 4; u++) {
                float axk = __shfl_sync(0xffffffffu, accx[u], k);
                float ayk = __shfl_sync(0xffffffffu, accy[u], k);
                unsigned long long dx, dy;
                PACK_DUP(dx, axk);
                PACK_DUP(dy, ayk);
                FFMA2(o[u], dx, w0);
                FFMA2(o[u], dy, w1);
            }
        }
#pragma unroll
        for (int u = 0; u < 4; u++) {
            int nu = n0 + u;
            if (nu < N) {
                unsigned int u0, u1;
                UNPACK2(u0, u1, o[u]);
                g_ps2[(size_t)nu * 32 + lane] = __floats2half2_rn(
                    di[u] * fmaxf(__uint_as_float(u0), 0.f),
                    di[u] * fmaxf(__uint_as_float(u1), 0.f));
            }
        }
    }
}

// ============================================================
// Layer 3: agg(64 = one 128B row) @ W3(64x128) + b3, relu -> g_h3 (fp16)
// QUAD-node shared-weight GEMV: each ulonglong2 weight load feeds 4 nodes.
// ============================================================
__global__ void k_layer3(const float* __restrict__ W3,
                         const float* __restrict__ b3, int N) {
    __shared__ __align__(16) float sW[64 * 128];  // 32 KB
    __shared__ __align__(16) float sb[128];
    int t = threadIdx.x;
    for (int i = t; i < 64 * 128; i += blockDim.x) sW[i] = W3[i];
    if (t < 128) sb[t] = b3[t];
    __syncthreads();
    int lane = t & 31;
    int warp0 = (blockIdx.x * blockDim.x + t) >> 5;
    int nwarps = (gridDim.x * blockDim.x) >> 5;
    const ulonglong2* sWq = (const ulonglong2*)sW;
    int nquads = (N + 3) >> 2;
    for (int qd = warp0; qd < nquads; qd += nwarps) {
        int n0 = 4 * qd;
        int deg[4], base[4];
        float ax[4], ay[4];
        int dmax = 0;
#pragma unroll
        for (int u = 0; u < 4; u++) {
            int nu = n0 + u;
            deg[u] = (nu < N) ? min(g_deg[nu], MAXD) : 0;
            base[u] = nu * MAXD;
            ax[u] = 0.f; ay[u] = 0.f;
            dmax = max(dmax, deg[u]);
        }
        for (int j = 0; j < dmax; j++) {
#pragma unroll
            for (int u = 0; u < 4; u++) {
                if (j < deg[u]) {
                    float2 f = __half22float2(g_ps2[(size_t)g_slot[base[u] + j] * 32 + lane]);
                    ax[u] += f.x; ay[u] += f.y;
                }
            }
        }
        float di[4], accx[4], accy[4];
#pragma unroll
        for (int u = 0; u < 4; u++) {
            int nu = n0 + u;
            if (nu < N) {
                di[u] = g_dinv[nu];
                float2 self = __half22float2(g_ps2[(size_t)nu * 32 + lane]);
                accx[u] = di[u] * (ax[u] + self.x);
                accy[u] = di[u] * (ay[u] + self.y);
            } else {
                di[u] = 0.f; accx[u] = 0.f; accy[u] = 0.f;
            }
        }
        // Interleaved GEMV: each 2x(f32x2) weight load feeds all 4 nodes.
        unsigned long long o01[4], o23[4];
        {
            ulonglong2 bb = ((const ulonglong2*)sb)[lane];
#pragma unroll
            for (int u = 0; u < 4; u++) { o01[u] = bb.x; o23[u] = bb.y; }
        }
#pragma unroll
        for (int k = 0; k < 32; k++) {
            ulonglong2 wu = sWq[(2 * k) * 32 + lane];     // W3[2k][4l..4l+3]
            ulonglong2 wv = sWq[(2 * k + 1) * 32 + lane]; // W3[2k+1][4l..4l+3]
#pragma unroll
            for (int u = 0; u < 4; u++) {
                float axk = __shfl_sync(0xffffffffu, accx[u], k);
                float ayk = __shfl_sync(0xffffffffu, accy[u], k);
                unsigned long long dx, dy;
                PACK_DUP(dx, axk);
                PACK_DUP(dy, ayk);
                FFMA2(o01[u], dx, wu.x);
                FFMA2(o23[u], dx, wu.y);
                FFMA2(o01[u], dy, wv.x);
                FFMA2(o23[u], dy, wv.y);
            }
        }
#pragma unroll
        for (int u = 0; u < 4; u++) {
            int nu = n0 + u;
            if (nu < N) {
                unsigned int u0, u1, u2, u3;
                UNPACK2(u0, u1, o01[u]);
                UNPACK2(u2, u3, o23[u]);
                __half2 h0 = __floats2half2_rn(fmaxf(__uint_as_float(u0), 0.f),
                                               fmaxf(__uint_as_float(u1), 0.f));
                __half2 h1 = __floats2half2_rn(fmaxf(__uint_as_float(u2), 0.f),
                                               fmaxf(__uint_as_float(u3), 0.f));
                uint2 st;
                st.x = *reinterpret_cast<unsigned int*>(&h0);
                st.y = *reinterpret_cast<unsigned int*>(&h1);
                ((uint2*)(g_h3 + (size_t)nu * 64))[lane] = st;
            }
        }
    }
}

// ============================================================
// Pool (mean; batch sorted) + MLP head. 64 threads per graph.
// ============================================================
__device__ __forceinline__ int lb_idx(const void* b, int n, int v, int is64) {
    int lo = 0, hi = n;
    while (lo < hi) {
        int m = (lo + hi) >> 1;
        if (idx_at(b, m, is64) < v) lo = m + 1; else hi = m;
    }
    return lo;
}

__global__ void k_poolhead(const void* __restrict__ batch, int N,
                           const float* __restrict__ Wf1, const float* __restrict__ bf1,
                           const float* __restrict__ Wf2, const float* __restrict__ bf2,
                           float* __restrict__ out) {
    __shared__ float sp[128];
    __shared__ float sz[32];
    int g = blockIdx.x;
    int t = threadIdx.x;   // 0..63, owns half2 feature pair t
    int is64 = g_is64;
    int lo = lb_idx(batch, N, g, is64);
    int hi = lb_idx(batch, N, g + 1, is64);
    float ax = 0.f, ay = 0.f;
    int i = lo;
    for (; i + 2 <= hi; i += 2) {
        float2 f0 = __half22float2(g_h3[(size_t)(i + 0) * 64 + t]);
        float2 f1 = __half22float2(g_h3[(size_t)(i + 1) * 64 + t]);
        ax += f0.x + f1.x;
        ay += f0.y + f1.y;
    }
    if (i < hi) {
        float2 f = __half22float2(g_h3[(size_t)i * 64 + t]);
        ax += f.x; ay += f.y;
    }
    float inv = 1.0f / fmaxf((float)(hi - lo), 1.0f);
    sp[2 * t]     = ax * inv;
    sp[2 * t + 1] = ay * inv;
    __syncthreads();
    if (t < 32) {
        float z = __ldg(&bf1[t]);
#pragma unroll 8
        for (int k = 0; k < 128; k++) z += sp[k] * __ldg(&Wf1[k * 32 + t]);
        sz[t] = fmaxf(z, 0.f);
    }
    __syncthreads();
    if (t < 4) {
        float o = __ldg(&bf2[t]);
#pragma unroll
        for (int k = 0; k < 32; k++) o += sz[k] * __ldg(&Wf2[k * 4 + t]);
        out[g * 4 + t] = o;
    }
}

// ============================================================
extern "C" void kernel_launch(void* const* d_in, const int* in_sizes, int n_in,
                              void* d_out, int out_size) {
    const float* x     = (const float*)d_in[0];
    const void*  ei    = d_in[1];
    const void*  batch = d_in[2];
    const float* W1 = (const float*)d_in[3];  const float* b1 = (const float*)d_in[4];
    const float* W2 = (const float*)d_in[5];  const float* b2 = (const float*)d_in[6];
    const float* W3 = (const float*)d_in[7];  const float* b3 = (const float*)d_in[8];
    const float* Wf1 = (const float*)d_in[9];  const float* bf1 = (const float*)d_in[10];
    const float* Wf2 = (const float*)d_in[11]; const float* bf2 = (const float*)d_in[12];
    float* out = (float*)d_out;

    int N = in_sizes[0] / 3;
    int E = in_sizes[1] / 2;
    int G = out_size / 4;

    k_prep<<<(N + 255) / 256, 256>>>((const int*)ei, E, N);
    k_fill<<<(E + 255) / 256, 256>>>(ei, E, N);
    k_scale<<<(N + 255) / 256, 256>>>(x, N);

    k_layer1<<<888, 256>>>(W1, b1, N);      // dual-node (measured best)
    k_layer2<<<888, 256>>>(W2, b2, N);      // quad-node shared-weight GEMV
    k_layer3<<<888, 256>>>(W3, b3, N);      // quad-node shared-weight GEMV

    k_poolhead<<<G, 64>>>(batch, N, Wf1, bf1, Wf2, bf2, out);
}

// round 17
// speedup vs baseline: 2.7327x; 1.0180x over previous
#include <cuda_runtime.h>
#include <cuda_fp16.h>
#include <math.h>

// Problem dims (fixed by the reference): N=50000, E=800000, G=512.
#define NMAX 50048
#define GMAX 512
#define MAXD 96     // per-node bucket capacity; deg ~ Poisson(16), P(>=96) ~ 0

// ---- packed fp32x2 helpers (sm_103a FFMA2; exact fp32) ----
#define FFMA2(d, a, b) \
    asm("fma.rn.f32x2 %0, %1, %2, %0;" : "+l"(d) : "l"(a), "l"(b))
#define PACK_DUP(d, x) \
    asm("mov.b64 %0, {%1, %1};" : "=l"(d) : "r"(__float_as_uint(x)))
#define UNPACK2(lo, hi, d) \
    asm("mov.b64 {%0, %1}, %2;" : "=r"(lo), "=r"(hi) : "l"(d))

// ---- scratch (device globals; no allocation allowed) ----
__device__ int     g_is64;               // 1 if index buffers are int64
__device__ int     g_deg[NMAX];
__device__ float   g_dinv[NMAX];
__device__ float4  g_px[NMAX];           // dinv[u] * x[u] padded to float4 (w=0)
__device__ int     g_slot[NMAX * MAXD];  // bucketed CSR-by-dst (src only)
__device__ __half2 g_ps1[NMAX * 16];     // dinv[u] * relu(h1[u])  (32 fp16)
__device__ __half2 g_ps2[NMAX * 32];     // dinv[u] * relu(h2[u])  (64 fp16)
__device__ __half2 g_h3[NMAX * 64];      // relu(h3[u])            (128 fp16)

__device__ __forceinline__ int idx_at(const void* p, long long i, int is64) {
    if (is64) return (int)((const long long*)p)[i];
    return ((const int*)p)[i];
}
__device__ __forceinline__ int clampi(int v, int lo, int hi) {
    return v < lo ? lo : (v > hi ? hi : v);
}

// ============================================================
// 0) zero degrees + detect index dtype
// ============================================================
__global__ void k_prep(const int* __restrict__ ebuf, int E, int N) {
    int i = blockIdx.x * blockDim.x + threadIdx.x;
    if (i < N) g_deg[i] = 0;
    if (blockIdx.x == 0) {
        __shared__ int s_nz;
        if (threadIdx.x == 0) s_nz = 0;
        __syncthreads();
        int nz = 0;
        int stride = (2 * E) / 4096;
        for (int k = threadIdx.x; k < 4096; k += blockDim.x) {
            long long w = (long long)k * stride | 1LL;
            if (w < 2LL * E) nz |= (ebuf[w] != 0);
        }
        if (nz) atomicOr(&s_nz, 1);
        __syncthreads();
        if (threadIdx.x == 0) g_is64 = (s_nz == 0) ? 1 : 0;
    }
}

// 1) bucket scatter: count + fill in ONE pass
__global__ void k_fill(const void* __restrict__ ei, int E, int N) {
    int e = blockIdx.x * blockDim.x + threadIdx.x;
    if (e < E) {
        int is64 = g_is64;
        int s = clampi(idx_at(ei, e, is64), 0, N - 1);
        int d = clampi(idx_at(ei, (long long)E + e, is64), 0, N - 1);
        int c = atomicAdd(&g_deg[d], 1);
        if (c < MAXD) g_slot[d * MAXD + c] = s;
    }
}

// 2) dinv = rsqrt(deg+1); pre-scale node features into float4
__global__ void k_scale(const float* __restrict__ x, int N) {
    int i = blockIdx.x * blockDim.x + threadIdx.x;
    if (i < N) {
        float di = rsqrtf((float)g_deg[i] + 1.0f);  // +1 self-loop
        g_dinv[i] = di;
        g_px[i] = make_float4(di * x[i * 3], di * x[i * 3 + 1], di * x[i * 3 + 2], 0.f);
    }
}

// ============================================================
// Layer 1: agg(3) @ W1(3x32) + b1, relu, pre-scale -> g_ps1 (fp16)
// EIGHT nodes per warp, 4 lanes per node (lane = 4u + c):
// 32 independent gather chains/warp, 2-level 4-lane shuffle reduce,
// all lanes active in transform (lane c -> features 8c..8c+7).
// ============================================================
__global__ void __launch_bounds__(256) k_layer1(const float* __restrict__ W1,
                                                const float* __restrict__ b1, int N) {
    __shared__ __align__(16) float sW[96];
    __shared__ __align__(16) float sb[32];
    int t = threadIdx.x;
    if (t < 96) sW[t] = W1[t];
    if (t < 32) sb[t] = b1[t];
    __syncthreads();
    int lane = t & 31;
    int u = lane >> 2;          // node sub-index 0..7
    int c = lane & 3;           // edge phase / output chunk
    int warp0 = (blockIdx.x * blockDim.x + t) >> 5;
    int nwarps = (gridDim.x * blockDim.x) >> 5;
    int ngroups = (N + 7) >> 3;
    const float4* sW4 = (const float4*)sW;   // sW row r: sW4[r*8 + i]
    const float4* sb4 = (const float4*)sb;
    for (int grp = warp0; grp < ngroups; grp += nwarps) {
        int node = grp * 8 + u;
        bool valid = (node < N);
        int deg = valid ? min(g_deg[node], MAXD) : 0;
        int base = node * MAXD;
        float ax = 0.f, ay = 0.f, az = 0.f;
        for (int j = c; j < deg; j += 4) {
            float4 p = g_px[g_slot[base + j]];
            ax += p.x; ay += p.y; az += p.z;
        }
        // reduce across the 4 lanes of this node
        ax += __shfl_xor_sync(0xffffffffu, ax, 1);
        ay += __shfl_xor_sync(0xffffffffu, ay, 1);
        az += __shfl_xor_sync(0xffffffffu, az, 1);
        ax += __shfl_xor_sync(0xffffffffu, ax, 2);
        ay += __shfl_xor_sync(0xffffffffu, ay, 2);
        az += __shfl_xor_sync(0xffffffffu, az, 2);
        if (valid) {
            float di = g_dinv[node];
            float4 self = g_px[node];
            float a0 = di * (ax + self.x);
            float a1 = di * (ay + self.y);
            float a2 = di * (az + self.z);
            // lane c computes output features 8c..8c+7
            float4 w0a = sW4[c * 2],      w0b = sW4[c * 2 + 1];       // W1 row0
            float4 w1a = sW4[8 + c * 2],  w1b = sW4[8 + c * 2 + 1];   // W1 row1
            float4 w2a = sW4[16 + c * 2], w2b = sW4[16 + c * 2 + 1];  // W1 row2
            float4 bba = sb4[c * 2],      bbb = sb4[c * 2 + 1];
            float o0 = bba.x + a0 * w0a.x + a1 * w1a.x + a2 * w2a.x;
            float o1 = bba.y + a0 * w0a.y + a1 * w1a.y + a2 * w2a.y;
            float o2 = bba.z + a0 * w0a.z + a1 * w1a.z + a2 * w2a.z;
            float o3 = bba.w + a0 * w0a.w + a1 * w1a.w + a2 * w2a.w;
            float o4 = bbb.x + a0 * w0b.x + a1 * w1b.x + a2 * w2b.x;
            float o5 = bbb.y + a0 * w0b.y + a1 * w1b.y + a2 * w2b.y;
            float o6 = bbb.z + a0 * w0b.z + a1 * w1b.z + a2 * w2b.z;
            float o7 = bbb.w + a0 * w0b.w + a1 * w1b.w + a2 * w2b.w;
            __half2 h0 = __floats2half2_rn(di * fmaxf(o0, 0.f), di * fmaxf(o1, 0.f));
            __half2 h1 = __floats2half2_rn(di * fmaxf(o2, 0.f), di * fmaxf(o3, 0.f));
            __half2 h2 = __floats2half2_rn(di * fmaxf(o4, 0.f), di * fmaxf(o5, 0.f));
            __half2 h3 = __floats2half2_rn(di * fmaxf(o6, 0.f), di * fmaxf(o7, 0.f));
            uint4 st;
            st.x = *reinterpret_cast<unsigned int*>(&h0);
            st.y = *reinterpret_cast<unsigned int*>(&h1);
            st.z = *reinterpret_cast<unsigned int*>(&h2);
            st.w = *reinterpret_cast<unsigned int*>(&h3);
            ((uint4*)(g_ps1 + (size_t)node * 16))[c] = st;
        }
    }
}

// ============================================================
// Layer 2: agg(32) @ W2(32x64) + b2, relu, pre-scale -> g_ps2 (fp16)
// QUAD-node shared-weight GEMV (R16 measured best).
// ============================================================
__global__ void k_layer2(const float* __restrict__ W2,
                         const float* __restrict__ b2, int N) {
    __shared__ __align__(16) float sW[32 * 64];   // 8 KB
    __shared__ __align__(16) float sb[64];
    int t = threadIdx.x;
    for (int i = t; i < 32 * 64; i += blockDim.x) sW[i] = W2[i];
    if (t < 64) sb[t] = b2[t];
    __syncthreads();
    int lane = t & 31;
    int warp0 = (blockIdx.x * blockDim.x + t) >> 5;
    int nwarps = (gridDim.x * blockDim.x) >> 5;
    int q = lane & 15, p = lane >> 4;
    const unsigned long long* sWp = (const unsigned long long*)sW;
    int nquads = (N + 3) >> 2;
    for (int qd = warp0; qd < nquads; qd += nwarps) {
        int n0 = 4 * qd;
        int deg[4], base[4];
        float ax[4], ay[4];
        int dmax = 0;
#pragma unroll
        for (int u = 0; u < 4; u++) {
            int nu = n0 + u;
            deg[u] = (nu < N) ? min(g_deg[nu], MAXD) : 0;
            base[u] = nu * MAXD;
            ax[u] = 0.f; ay[u] = 0.f;
            dmax = max(dmax, deg[u]);
        }
        for (int j = p; j < dmax; j += 2) {
#pragma unroll
            for (int u = 0; u < 4; u++) {
                if (j < deg[u]) {
                    float2 f = __half22float2(g_ps1[(size_t)g_slot[base[u] + j] * 16 + q]);
                    ax[u] += f.x; ay[u] += f.y;
                }
            }
        }
        float di[4], accx[4], accy[4];
#pragma unroll
        for (int u = 0; u < 4; u++) {
            ax[u] += __shfl_xor_sync(0xffffffffu, ax[u], 16);
            ay[u] += __shfl_xor_sync(0xffffffffu, ay[u], 16);
            int nu = n0 + u;
            if (nu < N) {
                di[u] = g_dinv[nu];
                float2 self = __half22float2(g_ps1[(size_t)nu * 16 + q]);
                accx[u] = di[u] * (ax[u] + self.x);
                accy[u] = di[u] * (ay[u] + self.y);
            } else {
                di[u] = 0.f; accx[u] = 0.f; accy[u] = 0.f;
            }
        }
        unsigned long long o[4];
        unsigned long long binit = ((const unsigned long long*)sb)[lane];
#pragma unroll
        for (int u = 0; u < 4; u++) o[u] = binit;
#pragma unroll
        for (int k = 0; k < 16; k++) {
            unsigned long long w0 = sWp[(2 * k) * 32 + lane];
            unsigned long long w1 = sWp[(2 * k + 1) * 32 + lane];
#pragma unroll
            for (int u = 0; u < 4; u++) {
                float axk = __shfl_sync(0xffffffffu, accx[u], k);
                float ayk = __shfl_sync(0xffffffffu, accy[u], k);
                unsigned long long dx, dy;
                PACK_DUP(dx, axk);
                PACK_DUP(dy, ayk);
                FFMA2(o[u], dx, w0);
                FFMA2(o[u], dy, w1);
            }
        }
#pragma unroll
        for (int u = 0; u < 4; u++) {
            int nu = n0 + u;
            if (nu < N) {
                unsigned int u0, u1;
                UNPACK2(u0, u1, o[u]);
                g_ps2[(size_t)nu * 32 + lane] = __floats2half2_rn(
                    di[u] * fmaxf(__uint_as_float(u0), 0.f),
                    di[u] * fmaxf(__uint_as_float(u1), 0.f));
            }
        }
    }
}

// ============================================================
// Layer 3: agg(64 = one 128B row) @ W3(64x128) + b3, relu -> g_h3 (fp16)
// QUAD-node shared-weight GEMV (R16 measured best).
// ============================================================
__global__ void k_layer3(const float* __restrict__ W3,
                         const float* __restrict__ b3, int N) {
    __shared__ __align__(16) float sW[64 * 128];  // 32 KB
    __shared__ __align__(16) float sb[128];
    int t = threadIdx.x;
    for (int i = t; i < 64 * 128; i += blockDim.x) sW[i] = W3[i];
    if (t < 128) sb[t] = b3[t];
    __syncthreads();
    int lane = t & 31;
    int warp0 = (blockIdx.x * blockDim.x + t) >> 5;
    int nwarps = (gridDim.x * blockDim.x) >> 5;
    const ulonglong2* sWq = (const ulonglong2*)sW;
    int nquads = (N + 3) >> 2;
    for (int qd = warp0; qd < nquads; qd += nwarps) {
        int n0 = 4 * qd;
        int deg[4], base[4];
        float ax[4], ay[4];
        int dmax = 0;
#pragma unroll
        for (int u = 0; u < 4; u++) {
            int nu = n0 + u;
            deg[u] = (nu < N) ? min(g_deg[nu], MAXD) : 0;
            base[u] = nu * MAXD;
            ax[u] = 0.f; ay[u] = 0.f;
            dmax = max(dmax, deg[u]);
        }
        for (int j = 0; j < dmax; j++) {
#pragma unroll
            for (int u = 0; u < 4; u++) {
                if (j < deg[u]) {
                    float2 f = __half22float2(g_ps2[(size_t)g_slot[base[u] + j] * 32 + lane]);
                    ax[u] += f.x; ay[u] += f.y;
                }
            }
        }
        float di[4], accx[4], accy[4];
#pragma unroll
        for (int u = 0; u < 4; u++) {
            int nu = n0 + u;
            if (nu < N) {
                di[u] = g_dinv[nu];
                float2 self = __half22float2(g_ps2[(size_t)nu * 32 + lane]);
                accx[u] = di[u] * (ax[u] + self.x);
                accy[u] = di[u] * (ay[u] + self.y);
            } else {
                di[u] = 0.f; accx[u] = 0.f; accy[u] = 0.f;
            }
        }
        unsigned long long o01[4], o23[4];
        {
            ulonglong2 bb = ((const ulonglong2*)sb)[lane];
#pragma unroll
            for (int u = 0; u < 4; u++) { o01[u] = bb.x; o23[u] = bb.y; }
        }
#pragma unroll
        for (int k = 0; k < 32; k++) {
            ulonglong2 wu = sWq[(2 * k) * 32 + lane];
            ulonglong2 wv = sWq[(2 * k + 1) * 32 + lane];
#pragma unroll
            for (int u = 0; u < 4; u++) {
                float axk = __shfl_sync(0xffffffffu, accx[u], k);
                float ayk = __shfl_sync(0xffffffffu, accy[u], k);
                unsigned long long dx, dy;
                PACK_DUP(dx, axk);
                PACK_DUP(dy, ayk);
                FFMA2(o01[u], dx, wu.x);
                FFMA2(o23[u], dx, wu.y);
                FFMA2(o01[u], dy, wv.x);
                FFMA2(o23[u], dy, wv.y);
            }
        }
#pragma unroll
        for (int u = 0; u < 4; u++) {
            int nu = n0 + u;
            if (nu < N) {
                unsigned int u0, u1, u2, u3;
                UNPACK2(u0, u1, o01[u]);
                UNPACK2(u2, u3, o23[u]);
                __half2 h0 = __floats2half2_rn(fmaxf(__uint_as_float(u0), 0.f),
                                               fmaxf(__uint_as_float(u1), 0.f));
                __half2 h1 = __floats2half2_rn(fmaxf(__uint_as_float(u2), 0.f),
                                               fmaxf(__uint_as_float(u3), 0.f));
                uint2 st;
                st.x = *reinterpret_cast<unsigned int*>(&h0);
                st.y = *reinterpret_cast<unsigned int*>(&h1);
                ((uint2*)(g_h3 + (size_t)nu * 64))[lane] = st;
            }
        }
    }
}

// ============================================================
// Pool (mean; batch sorted) + MLP head. 64 threads per graph.
// ============================================================
__device__ __forceinline__ int lb_idx(const void* b, int n, int v, int is64) {
    int lo = 0, hi = n;
    while (lo < hi) {
        int m = (lo + hi) >> 1;
        if (idx_at(b, m, is64) < v) lo = m + 1; else hi = m;
    }
    return lo;
}

__global__ void k_poolhead(const void* __restrict__ batch, int N,
                           const float* __restrict__ Wf1, const float* __restrict__ bf1,
                           const float* __restrict__ Wf2, const float* __restrict__ bf2,
                           float* __restrict__ out) {
    __shared__ float sp[128];
    __shared__ float sz[32];
    int g = blockIdx.x;
    int t = threadIdx.x;   // 0..63, owns half2 feature pair t
    int is64 = g_is64;
    int lo = lb_idx(batch, N, g, is64);
    int hi = lb_idx(batch, N, g + 1, is64);
    float ax = 0.f, ay = 0.f;
    int i = lo;
    for (; i + 2 <= hi; i += 2) {
        float2 f0 = __half22float2(g_h3[(size_t)(i + 0) * 64 + t]);
        float2 f1 = __half22float2(g_h3[(size_t)(i + 1) * 64 + t]);
        ax += f0.x + f1.x;
        ay += f0.y + f1.y;
    }
    if (i < hi) {
        float2 f = __half22float2(g_h3[(size_t)i * 64 + t]);
        ax += f.x; ay += f.y;
    }
    float inv = 1.0f / fmaxf((float)(hi - lo), 1.0f);
    sp[2 * t]     = ax * inv;
    sp[2 * t + 1] = ay * inv;
    __syncthreads();
    if (t < 32) {
        float z = __ldg(&bf1[t]);
#pragma unroll 8
        for (int k = 0; k < 128; k++) z += sp[k] * __ldg(&Wf1[k * 32 + t]);
        sz[t] = fmaxf(z, 0.f);
    }
    __syncthreads();
    if (t < 4) {
        float o = __ldg(&bf2[t]);
#pragma unroll
        for (int k = 0; k < 32; k++) o += sz[k] * __ldg(&Wf2[k * 4 + t]);
        out[g * 4 + t] = o;
    }
}

// ============================================================
extern "C" void kernel_launch(void* const* d_in, const int* in_sizes, int n_in,
                              void* d_out, int out_size) {
    const float* x     = (const float*)d_in[0];
    const void*  ei    = d_in[1];
    const void*  batch = d_in[2];
    const float* W1 = (const float*)d_in[3];  const float* b1 = (const float*)d_in[4];
    const float* W2 = (const float*)d_in[5];  const float* b2 = (const float*)d_in[6];
    const float* W3 = (const float*)d_in[7];  const float* b3 = (const float*)d_in[8];
    const float* Wf1 = (const float*)d_in[9];  const float* bf1 = (const float*)d_in[10];
    const float* Wf2 = (const float*)d_in[11]; const float* bf2 = (const float*)d_in[12];
    float* out = (float*)d_out;

    int N = in_sizes[0] / 3;
    int E = in_sizes[1] / 2;
    int G = out_size / 4;

    k_prep<<<(N + 255) / 256, 256>>>((const int*)ei, E, N);
    k_fill<<<(E + 255) / 256, 256>>>(ei, E, N);
    k_scale<<<(N + 255) / 256, 256>>>(x, N);

    k_layer1<<<888, 256>>>(W1, b1, N);      // 8-node/warp, 4-lane groups
    k_layer2<<<888, 256>>>(W2, b2, N);      // quad-node shared-weight GEMV
    k_layer3<<<888, 256>>>(W3, b3, N);      // quad-node shared-weight GEMV

    k_poolhead<<<G, 64>>>(batch, N, Wf1, bf1, Wf2, bf2, out);
}